// round 15
// baseline (speedup 1.0000x reference)
#include <cuda_runtime.h>
#include <cuda_fp16.h>
#include <cstdint>

// ============================================================================
// NCMOpenMax: probas = softmax(cos(X, muK), axis=1)
//   X [262144,128] f32, muK [512,128] f32, out [262144,512] f32
//
// fp16 mma.sync.m16n8k16, persistent CTAs (1/SM, 256 thr = 8 warps).
// B entirely in registers (128 regs/thread). Tile = 32 rows x 512 classes.
// X rows normalized during staging (IEEE sqrt+div) -> exp arg = acc*log2e.
// ONE barrier per tile; pass2(t-1) fuses into mma(t) via C=0 fresh-write
// first mma (WAR on acc regs, no zero-init MOVs):
//   per tile: ldg(t+1) -> [pass2(t-1) || mma(t)] -> exp(t) -> stage(t+1) -> bar
// A and rs parity double-buffered.
// R15 FIX: tail pass2 reads rs parity (p ? RS0 : RS1) — the buffer the LAST
// exp_tile wrote (p flips after writing). R12-R14 read the stale buffer,
// normalizing each CTA's final tile by the previous tile's denominators
// (the stable 7.016e-4 rel_err).
// ============================================================================

static constexpr int DDIM = 128;
static constexpr int KCLS = 512;
static constexpr int BM   = 32;

// B fragments fp16: [s(8)][t(64)][lane(32)] x uint2 (4 halves)
__device__ __half g_bfrag[8 * 64 * 32 * 4];   // 128 KB

// ---- smem layout (bytes) ----
static constexpr int A_STRIDE = 272;              // 256B row + 16B pad
static constexpr int A_BYTES  = BM * A_STRIDE;    // 8704
static constexpr int SM_A0    = 0;
static constexpr int SM_A1    = A_BYTES;          // 8704
static constexpr int SM_RS0   = 2 * A_BYTES;      // 17408 (32 x 8 f32)
static constexpr int SM_RS1   = SM_RS0 + 1024;    // 18432
static constexpr int SM_TOTAL = SM_RS1 + 1024;    // 19456

__device__ __forceinline__ uint32_t smem_u32(const void* p) {
    uint32_t a;
    asm("{ .reg .u64 t; cvta.to.shared.u64 t, %1; cvt.u32.u64 %0, t; }"
        : "=r"(a) : "l"(p));
    return a;
}

__device__ __forceinline__ void mma_f16(float* d, const uint32_t* a,
                                        uint32_t b0, uint32_t b1) {
    asm volatile(
        "mma.sync.aligned.m16n8k16.row.col.f32.f16.f16.f32 "
        "{%0,%1,%2,%3},{%4,%5,%6,%7},{%8,%9},{%0,%1,%2,%3};"
        : "+f"(d[0]), "+f"(d[1]), "+f"(d[2]), "+f"(d[3])
        : "r"(a[0]), "r"(a[1]), "r"(a[2]), "r"(a[3]), "r"(b0), "r"(b1));
}

// fresh-write form: D = A*B + 0  (acc regs written, not read)
__device__ __forceinline__ void mma_f16_z(float* d, const uint32_t* a,
                                          uint32_t b0, uint32_t b1) {
    asm volatile(
        "mma.sync.aligned.m16n8k16.row.col.f32.f16.f16.f32 "
        "{%0,%1,%2,%3},{%4,%5,%6,%7},{%8,%9},{%10,%11,%12,%13};"
        : "=f"(d[0]), "=f"(d[1]), "=f"(d[2]), "=f"(d[3])
        : "r"(a[0]), "r"(a[1]), "r"(a[2]), "r"(a[3]), "r"(b0), "r"(b1),
          "f"(0.f), "f"(0.f), "f"(0.f), "f"(0.f));
}

__device__ __forceinline__ float ex2f(float x) {
    float r;
    asm("ex2.approx.ftz.f32 %0, %1;" : "=f"(r) : "f"(x));
    return r;
}
__device__ __forceinline__ void stg_cs(float* p, float4 v) {
    asm volatile("st.global.cs.v4.f32 [%0], {%1,%2,%3,%4};"
                 :: "l"(p), "f"(v.x), "f"(v.y), "f"(v.z), "f"(v.w)
                 : "memory");
}

constexpr float LOG2E = 1.4426950408889634f;

// ---------------- prep: normalize muK -> permuted fp16 fragments -----------

__global__ void ncm_prep(const float* __restrict__ muK) {
    __shared__ float pp[4];
    int n = blockIdx.x;       // class (output column)
    int k = threadIdx.x;      // feature
    float v = muK[n * DDIM + k];
    float ss = v * v;
    #pragma unroll
    for (int o = 16; o > 0; o >>= 1)
        ss += __shfl_xor_sync(0xffffffffu, ss, o);
    if ((k & 31) == 0) pp[k >> 5] = ss;
    __syncthreads();
    float inv = 1.0f / fmaxf(sqrtf(pp[0] + pp[1] + pp[2] + pp[3]), 1e-8f);

    // column permutation (validated R5/R10)
    int wb = n >> 6, nl = n & 63;
    int u  = nl >> 4, j = nl & 15;
    int kq = j >> 2, hi = (j >> 1) & 1, e = j & 1;
    int F  = wb * 64 + u * 16 + hi * 8 + kq * 2 + e;
    int t  = F >> 3;
    int fc = F & 7;

    int s    = k >> 4;
    int kk   = k & 15;
    int lane = fc * 4 + ((kk & 7) >> 1);
    int idx  = ((kk >= 8) ? 2 : 0) + (kk & 1);
    g_bfrag[(((s * 64 + t) * 32 + lane) << 2) + idx] = __float2half_rn(v * inv);
}

// ---------------- main: persistent GEMM + fused softmax ----------------

__global__ void __launch_bounds__(256, 1)
ncm_main(const float* __restrict__ X, float* __restrict__ out,
         int tiles, int nct) {
    extern __shared__ char smem[];
    const uint32_t sb = smem_u32(smem);
    const int tid  = threadIdx.x;
    const int lane = tid & 31;
    const int wid  = tid >> 5;
    const int g    = lane >> 2;
    const int kq   = lane & 3;

    // ldmatrix lane addressing (x4: two 8-row mats x two 8-col k-halves)
    const int m_    = lane >> 3;
    const int lrow  = ((m_ & 1) << 3) + (lane & 7);
    const int lkoff = (m_ >> 1) << 4;

    // ---- B into registers: warp wid owns classes [wid*64, wid*64+64) ----
    uint2 breg[8][8];
    {
        const uint2* bsrc = reinterpret_cast<const uint2*>(g_bfrag);
        #pragma unroll
        for (int s = 0; s < 8; s++)
            #pragma unroll
            for (int t = 0; t < 8; t++)
                breg[s][t] = bsrc[(s * 64 + wid * 8 + t) * 32 + lane];
    }

    const int r = tid >> 3;   // A row owned on load path (32 rows, 8 thr/row)
    const int q = tid & 7;    // float4 phase within row

    auto ldgA = [&](int t_, float4* x) {
        const float4* src = reinterpret_cast<const float4*>(X)
                            + ((size_t)t_ * BM + r) * 32;
        #pragma unroll
        for (int i = 0; i < 4; i++) x[i] = src[q + 8 * i];
    };

    // stage: normalize row (IEEE sqrt + div), cvt f16, STS
    auto stage = [&](const float4* x, int abuf) {
        float ss = 0.f;
        #pragma unroll
        for (int i = 0; i < 4; i++)
            ss += x[i].x * x[i].x + x[i].y * x[i].y +
                  x[i].z * x[i].z + x[i].w * x[i].w;
        ss += __shfl_xor_sync(0xffffffffu, ss, 1);
        ss += __shfl_xor_sync(0xffffffffu, ss, 2);
        ss += __shfl_xor_sync(0xffffffffu, ss, 4);
        const float inv = 1.0f / fmaxf(sqrtf(ss), 1e-8f);
        char* adst = smem + abuf + r * A_STRIDE;
        #pragma unroll
        for (int i = 0; i < 4; i++) {
            __half2 h0 = __floats2half2_rn(x[i].x * inv, x[i].y * inv);
            __half2 h1 = __floats2half2_rn(x[i].z * inv, x[i].w * inv);
            uint2 u2;
            u2.x = *reinterpret_cast<uint32_t*>(&h0);
            u2.y = *reinterpret_cast<uint32_t*>(&h1);
            *reinterpret_cast<uint2*>(adst + (q + 8 * i) * 8) = u2;
        }
    };

    // mma: fresh-write first k-step (acc regs not read -> WAR fusion w/ pass2)
    auto mma_tile = [&](float (*acc0)[4], float (*acc1)[4], int abuf) {
        const uint32_t abase = sb + abuf;
        #pragma unroll
        for (int s = 0; s < 8; s++) {
            uint32_t a0[4], a1[4];
            uint32_t ad0 = abase + (uint32_t)(lrow * A_STRIDE + s * 32 + lkoff);
            asm volatile(
                "ldmatrix.sync.aligned.m8n8.x4.shared.b16 {%0,%1,%2,%3},[%4];"
                : "=r"(a0[0]), "=r"(a0[1]), "=r"(a0[2]), "=r"(a0[3])
                : "r"(ad0));
            asm volatile(
                "ldmatrix.sync.aligned.m8n8.x4.shared.b16 {%0,%1,%2,%3},[%4];"
                : "=r"(a1[0]), "=r"(a1[1]), "=r"(a1[2]), "=r"(a1[3])
                : "r"(ad0 + 16 * A_STRIDE));
            #pragma unroll
            for (int t = 0; t < 8; t++) {
                if (s == 0) {
                    mma_f16_z(acc0[t], a0, breg[s][t].x, breg[s][t].y);
                    mma_f16_z(acc1[t], a1, breg[s][t].x, breg[s][t].y);
                } else {
                    mma_f16(acc0[t], a0, breg[s][t].x, breg[s][t].y);
                    mma_f16(acc1[t], a1, breg[s][t].x, breg[s][t].y);
                }
            }
        }
    };

    auto exp_tile = [&](float (*acc0)[4], float (*acc1)[4], int rsoff) {
        float* rs = reinterpret_cast<float*>(smem + rsoff);
        #pragma unroll
        for (int sl = 0; sl < 2; sl++) {
            float (*acc)[4] = sl ? acc1 : acc0;
            #pragma unroll
            for (int h = 0; h < 2; h++) {
                const int row = sl * 16 + h * 8 + g;
                float psum = 0.f;
                #pragma unroll
                for (int t = 0; t < 8; t++) {
                    float e0 = ex2f(acc[t][h * 2 + 0] * LOG2E);
                    float e1 = ex2f(acc[t][h * 2 + 1] * LOG2E);
                    acc[t][h * 2 + 0] = e0;
                    acc[t][h * 2 + 1] = e1;
                    psum += e0 + e1;
                }
                psum += __shfl_xor_sync(0xffffffffu, psum, 1);
                psum += __shfl_xor_sync(0xffffffffu, psum, 2);
                if (kq == 0) rs[row * 8 + wid] = psum;
            }
        }
    };

    auto pass2 = [&](float (*acc0)[4], float (*acc1)[4], int rsoff, int tile) {
        const float4* rsq = reinterpret_cast<const float4*>(smem + rsoff);
        #pragma unroll
        for (int sl = 0; sl < 2; sl++) {
            float (*acc)[4] = sl ? acc1 : acc0;
            #pragma unroll
            for (int h = 0; h < 2; h++) {
                const int row = sl * 16 + h * 8 + g;
                float4 d0 = rsq[row * 2];
                float4 d1 = rsq[row * 2 + 1];
                const float iv = 1.0f / (d0.x + d0.y + d0.z + d0.w +
                                         d1.x + d1.y + d1.z + d1.w);
                float* op = out + ((size_t)tile * BM + row) * KCLS
                                + wid * 64 + kq * 4;
                #pragma unroll
                for (int u = 0; u < 4; u++) {
                    float4 v;
                    v.x = acc[2 * u + 0][h * 2 + 0] * iv;
                    v.y = acc[2 * u + 0][h * 2 + 1] * iv;
                    v.z = acc[2 * u + 1][h * 2 + 0] * iv;
                    v.w = acc[2 * u + 1][h * 2 + 1] * iv;
                    stg_cs(op + u * 16, v);
                }
            }
        }
    };

    float acc0[8][4], acc1[8][4];
    float4 x[4];

    // ---- prologue: tile0 -> A0; mma+exp(t0); stage(t1 -> A1); bar ----
    int t = blockIdx.x;
    ldgA(t, x);
    stage(x, SM_A0);
    __syncthreads();

    {
        bool hn = (t + nct) < tiles;
        if (hn) ldgA(t + nct, x);
        mma_tile(acc0, acc1, SM_A0);
        exp_tile(acc0, acc1, SM_RS0);
        if (hn) stage(x, SM_A1);
        __syncthreads();
    }

    int tprev = t;
    t += nct;
    int p = 1;
    while (t < tiles) {
        const int abuf  = p ? SM_A1 : SM_A0;
        const int rsoff = p ? SM_RS1 : SM_RS0;
        const int rsold = p ? SM_RS0 : SM_RS1;
        const bool hn = (t + nct) < tiles;

        if (hn) ldgA(t + nct, x);

        // fused window: stores of tile tprev + mma of tile t (no barrier)
        pass2(acc0, acc1, rsold, tprev);
        mma_tile(acc0, acc1, abuf);

        exp_tile(acc0, acc1, rsoff);
        if (hn) stage(x, p ? SM_A0 : SM_A1);
        __syncthreads();

        tprev = t;
        t += nct;
        p ^= 1;
    }

    // tail: store last tile. Its exp_tile wrote rsoff with PRE-flip parity,
    // i.e. buffer (p ? SM_RS0 : SM_RS1) after the final p ^= 1.  [R15 FIX]
    pass2(acc0, acc1, p ? SM_RS0 : SM_RS1, tprev);
}

// ---------------- launch ----------------

extern "C" void kernel_launch(void* const* d_in, const int* in_sizes, int n_in,
                              void* d_out, int out_size) {
    const float* X   = (const float*)d_in[0];   // [N,128]
    const float* muK = (const float*)d_in[1];   // [512,128]
    float* out = (float*)d_out;                 // [N,512]

    static int sms = 0;
    if (!sms) {
        cudaDeviceGetAttribute(&sms, cudaDevAttrMultiProcessorCount, 0);
        if (sms <= 0) sms = 148;
        cudaFuncSetAttribute(ncm_main,
                             cudaFuncAttributeMaxDynamicSharedMemorySize,
                             SM_TOTAL);
    }

    int N = in_sizes[0] / DDIM;
    int tiles = N / BM;                  // 8192
    int nct = sms < tiles ? sms : tiles;

    ncm_prep<<<KCLS, DDIM>>>(muK);
    ncm_main<<<nct, 256, SM_TOTAL>>>(X, out, tiles, nct);
}

// round 16
// speedup vs baseline: 1.0405x; 1.0405x over previous
#include <cuda_runtime.h>
#include <cuda_fp16.h>
#include <cstdint>

// ============================================================================
// NCMOpenMax: probas = softmax(cos(X, muK), axis=1)
//   X [262144,128] f32, muK [512,128] f32, out [262144,512] f32
//
// fp16 mma.sync.m16n8k16, persistent CTAs (1/SM, 256 thr = 8 warps).
// B entirely in registers (128 regs/thread). Tile = 32 rows x 512 classes.
// A staged as x * (log2e/||x||) in fp16 -> GEMM result IS the ex2 argument:
// exp pass is a bare ex2 (64 FMUL/thread/tile deleted vs R15).
// ONE barrier per tile; pass2(t-1) fuses into mma(t) via C=0 fresh-write
// first mma (WAR on acc regs, no zero-init MOVs):
//   per tile: ldg(t+1) -> [pass2(t-1) || mma(t)] -> exp(t) -> stage(t+1) -> bar
// A and rs parity double-buffered; tail pass2 reads post-flip parity (R15 fix).
// IEEE sqrt/div (measured faster than approx). st.global.cs stores.
// softmax shift dropped: cos<=1, shift-invariant => exact.
// ============================================================================

static constexpr int DDIM = 128;
static constexpr int KCLS = 512;
static constexpr int BM   = 32;

// B fragments fp16: [s(8)][t(64)][lane(32)] x uint2 (4 halves)
__device__ __half g_bfrag[8 * 64 * 32 * 4];   // 128 KB

// ---- smem layout (bytes) ----
static constexpr int A_STRIDE = 272;              // 256B row + 16B pad
static constexpr int A_BYTES  = BM * A_STRIDE;    // 8704
static constexpr int SM_A0    = 0;
static constexpr int SM_A1    = A_BYTES;          // 8704
static constexpr int SM_RS0   = 2 * A_BYTES;      // 17408 (32 x 8 f32)
static constexpr int SM_RS1   = SM_RS0 + 1024;    // 18432
static constexpr int SM_TOTAL = SM_RS1 + 1024;    // 19456

__device__ __forceinline__ uint32_t smem_u32(const void* p) {
    uint32_t a;
    asm("{ .reg .u64 t; cvta.to.shared.u64 t, %1; cvt.u32.u64 %0, t; }"
        : "=r"(a) : "l"(p));
    return a;
}

__device__ __forceinline__ void mma_f16(float* d, const uint32_t* a,
                                        uint32_t b0, uint32_t b1) {
    asm volatile(
        "mma.sync.aligned.m16n8k16.row.col.f32.f16.f16.f32 "
        "{%0,%1,%2,%3},{%4,%5,%6,%7},{%8,%9},{%0,%1,%2,%3};"
        : "+f"(d[0]), "+f"(d[1]), "+f"(d[2]), "+f"(d[3])
        : "r"(a[0]), "r"(a[1]), "r"(a[2]), "r"(a[3]), "r"(b0), "r"(b1));
}

// fresh-write form: D = A*B + 0  (acc regs written, not read)
__device__ __forceinline__ void mma_f16_z(float* d, const uint32_t* a,
                                          uint32_t b0, uint32_t b1) {
    asm volatile(
        "mma.sync.aligned.m16n8k16.row.col.f32.f16.f16.f32 "
        "{%0,%1,%2,%3},{%4,%5,%6,%7},{%8,%9},{%10,%11,%12,%13};"
        : "=f"(d[0]), "=f"(d[1]), "=f"(d[2]), "=f"(d[3])
        : "r"(a[0]), "r"(a[1]), "r"(a[2]), "r"(a[3]), "r"(b0), "r"(b1),
          "f"(0.f), "f"(0.f), "f"(0.f), "f"(0.f));
}

__device__ __forceinline__ float ex2f(float x) {
    float r;
    asm("ex2.approx.ftz.f32 %0, %1;" : "=f"(r) : "f"(x));
    return r;
}
__device__ __forceinline__ void stg_cs(float* p, float4 v) {
    asm volatile("st.global.cs.v4.f32 [%0], {%1,%2,%3,%4};"
                 :: "l"(p), "f"(v.x), "f"(v.y), "f"(v.z), "f"(v.w)
                 : "memory");
}

constexpr float LOG2E = 1.4426950408889634f;

// ---------------- prep: normalize muK -> permuted fp16 fragments -----------

__global__ void ncm_prep(const float* __restrict__ muK) {
    __shared__ float pp[4];
    int n = blockIdx.x;       // class (output column)
    int k = threadIdx.x;      // feature
    float v = muK[n * DDIM + k];
    float ss = v * v;
    #pragma unroll
    for (int o = 16; o > 0; o >>= 1)
        ss += __shfl_xor_sync(0xffffffffu, ss, o);
    if ((k & 31) == 0) pp[k >> 5] = ss;
    __syncthreads();
    float inv = 1.0f / fmaxf(sqrtf(pp[0] + pp[1] + pp[2] + pp[3]), 1e-8f);

    // column permutation (validated R5/R10)
    int wb = n >> 6, nl = n & 63;
    int u  = nl >> 4, j = nl & 15;
    int kq = j >> 2, hi = (j >> 1) & 1, e = j & 1;
    int F  = wb * 64 + u * 16 + hi * 8 + kq * 2 + e;
    int t  = F >> 3;
    int fc = F & 7;

    int s    = k >> 4;
    int kk   = k & 15;
    int lane = fc * 4 + ((kk & 7) >> 1);
    int idx  = ((kk >= 8) ? 2 : 0) + (kk & 1);
    g_bfrag[(((s * 64 + t) * 32 + lane) << 2) + idx] = __float2half_rn(v * inv);
}

// ---------------- main: persistent GEMM + fused softmax ----------------

__global__ void __launch_bounds__(256, 1)
ncm_main(const float* __restrict__ X, float* __restrict__ out,
         int tiles, int nct) {
    extern __shared__ char smem[];
    const uint32_t sb = smem_u32(smem);
    const int tid  = threadIdx.x;
    const int lane = tid & 31;
    const int wid  = tid >> 5;
    const int g    = lane >> 2;
    const int kq   = lane & 3;

    // ldmatrix lane addressing (x4: two 8-row mats x two 8-col k-halves)
    const int m_    = lane >> 3;
    const int lrow  = ((m_ & 1) << 3) + (lane & 7);
    const int lkoff = (m_ >> 1) << 4;

    // ---- B into registers: warp wid owns classes [wid*64, wid*64+64) ----
    uint2 breg[8][8];
    {
        const uint2* bsrc = reinterpret_cast<const uint2*>(g_bfrag);
        #pragma unroll
        for (int s = 0; s < 8; s++)
            #pragma unroll
            for (int t = 0; t < 8; t++)
                breg[s][t] = bsrc[(s * 64 + wid * 8 + t) * 32 + lane];
    }

    const int r = tid >> 3;   // A row owned on load path (32 rows, 8 thr/row)
    const int q = tid & 7;    // float4 phase within row

    auto ldgA = [&](int t_, float4* x) {
        const float4* src = reinterpret_cast<const float4*>(X)
                            + ((size_t)t_ * BM + r) * 32;
        #pragma unroll
        for (int i = 0; i < 4; i++) x[i] = src[q + 8 * i];
    };

    // stage: scale row by log2e/||x|| (IEEE sqrt + div), cvt f16, STS
    auto stage = [&](const float4* x, int abuf) {
        float ss = 0.f;
        #pragma unroll
        for (int i = 0; i < 4; i++)
            ss += x[i].x * x[i].x + x[i].y * x[i].y +
                  x[i].z * x[i].z + x[i].w * x[i].w;
        ss += __shfl_xor_sync(0xffffffffu, ss, 1);
        ss += __shfl_xor_sync(0xffffffffu, ss, 2);
        ss += __shfl_xor_sync(0xffffffffu, ss, 4);
        const float inv = LOG2E / fmaxf(sqrtf(ss), 1e-8f);
        char* adst = smem + abuf + r * A_STRIDE;
        #pragma unroll
        for (int i = 0; i < 4; i++) {
            __half2 h0 = __floats2half2_rn(x[i].x * inv, x[i].y * inv);
            __half2 h1 = __floats2half2_rn(x[i].z * inv, x[i].w * inv);
            uint2 u2;
            u2.x = *reinterpret_cast<uint32_t*>(&h0);
            u2.y = *reinterpret_cast<uint32_t*>(&h1);
            *reinterpret_cast<uint2*>(adst + (q + 8 * i) * 8) = u2;
        }
    };

    // mma: fresh-write first k-step (acc regs not read -> WAR fusion w/ pass2)
    auto mma_tile = [&](float (*acc0)[4], float (*acc1)[4], int abuf) {
        const uint32_t abase = sb + abuf;
        #pragma unroll
        for (int s = 0; s < 8; s++) {
            uint32_t a0[4], a1[4];
            uint32_t ad0 = abase + (uint32_t)(lrow * A_STRIDE + s * 32 + lkoff);
            asm volatile(
                "ldmatrix.sync.aligned.m8n8.x4.shared.b16 {%0,%1,%2,%3},[%4];"
                : "=r"(a0[0]), "=r"(a0[1]), "=r"(a0[2]), "=r"(a0[3])
                : "r"(ad0));
            asm volatile(
                "ldmatrix.sync.aligned.m8n8.x4.shared.b16 {%0,%1,%2,%3},[%4];"
                : "=r"(a1[0]), "=r"(a1[1]), "=r"(a1[2]), "=r"(a1[3])
                : "r"(ad0 + 16 * A_STRIDE));
            #pragma unroll
            for (int t = 0; t < 8; t++) {
                if (s == 0) {
                    mma_f16_z(acc0[t], a0, breg[s][t].x, breg[s][t].y);
                    mma_f16_z(acc1[t], a1, breg[s][t].x, breg[s][t].y);
                } else {
                    mma_f16(acc0[t], a0, breg[s][t].x, breg[s][t].y);
                    mma_f16(acc1[t], a1, breg[s][t].x, breg[s][t].y);
                }
            }
        }
    };

    // exp pass: acc already holds log2e * cos -> bare ex2
    auto exp_tile = [&](float (*acc0)[4], float (*acc1)[4], int rsoff) {
        float* rs = reinterpret_cast<float*>(smem + rsoff);
        #pragma unroll
        for (int sl = 0; sl < 2; sl++) {
            float (*acc)[4] = sl ? acc1 : acc0;
            #pragma unroll
            for (int h = 0; h < 2; h++) {
                const int row = sl * 16 + h * 8 + g;
                float psum = 0.f;
                #pragma unroll
                for (int t = 0; t < 8; t++) {
                    float e0 = ex2f(acc[t][h * 2 + 0]);
                    float e1 = ex2f(acc[t][h * 2 + 1]);
                    acc[t][h * 2 + 0] = e0;
                    acc[t][h * 2 + 1] = e1;
                    psum += e0 + e1;
                }
                psum += __shfl_xor_sync(0xffffffffu, psum, 1);
                psum += __shfl_xor_sync(0xffffffffu, psum, 2);
                if (kq == 0) rs[row * 8 + wid] = psum;
            }
        }
    };

    auto pass2 = [&](float (*acc0)[4], float (*acc1)[4], int rsoff, int tile) {
        const float4* rsq = reinterpret_cast<const float4*>(smem + rsoff);
        #pragma unroll
        for (int sl = 0; sl < 2; sl++) {
            float (*acc)[4] = sl ? acc1 : acc0;
            #pragma unroll
            for (int h = 0; h < 2; h++) {
                const int row = sl * 16 + h * 8 + g;
                float4 d0 = rsq[row * 2];
                float4 d1 = rsq[row * 2 + 1];
                const float iv = 1.0f / (d0.x + d0.y + d0.z + d0.w +
                                         d1.x + d1.y + d1.z + d1.w);
                float* op = out + ((size_t)tile * BM + row) * KCLS
                                + wid * 64 + kq * 4;
                #pragma unroll
                for (int u = 0; u < 4; u++) {
                    float4 v;
                    v.x = acc[2 * u + 0][h * 2 + 0] * iv;
                    v.y = acc[2 * u + 0][h * 2 + 1] * iv;
                    v.z = acc[2 * u + 1][h * 2 + 0] * iv;
                    v.w = acc[2 * u + 1][h * 2 + 1] * iv;
                    stg_cs(op + u * 16, v);
                }
            }
        }
    };

    float acc0[8][4], acc1[8][4];
    float4 x[4];

    // ---- prologue: tile0 -> A0; mma+exp(t0); stage(t1 -> A1); bar ----
    int t = blockIdx.x;
    ldgA(t, x);
    stage(x, SM_A0);
    __syncthreads();

    {
        bool hn = (t + nct) < tiles;
        if (hn) ldgA(t + nct, x);
        mma_tile(acc0, acc1, SM_A0);
        exp_tile(acc0, acc1, SM_RS0);
        if (hn) stage(x, SM_A1);
        __syncthreads();
    }

    int tprev = t;
    t += nct;
    int p = 1;
    while (t < tiles) {
        const int abuf  = p ? SM_A1 : SM_A0;
        const int rsoff = p ? SM_RS1 : SM_RS0;
        const int rsold = p ? SM_RS0 : SM_RS1;
        const bool hn = (t + nct) < tiles;

        if (hn) ldgA(t + nct, x);

        // fused window: stores of tile tprev + mma of tile t (no barrier)
        pass2(acc0, acc1, rsold, tprev);
        mma_tile(acc0, acc1, abuf);

        exp_tile(acc0, acc1, rsoff);
        if (hn) stage(x, p ? SM_A0 : SM_A1);
        __syncthreads();

        tprev = t;
        t += nct;
        p ^= 1;
    }

    // tail: last exp_tile wrote pre-flip parity => read (p ? RS0 : RS1).
    pass2(acc0, acc1, p ? SM_RS0 : SM_RS1, tprev);
}

// ---------------- launch ----------------

extern "C" void kernel_launch(void* const* d_in, const int* in_sizes, int n_in,
                              void* d_out, int out_size) {
    const float* X   = (const float*)d_in[0];   // [N,128]
    const float* muK = (const float*)d_in[1];   // [512,128]
    float* out = (float*)d_out;                 // [N,512]

    static int sms = 0;
    if (!sms) {
        cudaDeviceGetAttribute(&sms, cudaDevAttrMultiProcessorCount, 0);
        if (sms <= 0) sms = 148;
        cudaFuncSetAttribute(ncm_main,
                             cudaFuncAttributeMaxDynamicSharedMemorySize,
                             SM_TOTAL);
    }

    int N = in_sizes[0] / DDIM;
    int tiles = N / BM;                  // 8192
    int nct = sms < tiles ? sms : tiles;

    ncm_prep<<<KCLS, DDIM>>>(muK);
    ncm_main<<<nct, 256, SM_TOTAL>>>(X, out, tiles, nct);
}